// round 5
// baseline (speedup 1.0000x reference)
#include <cuda_runtime.h>
#include <math.h>

#define BB 16
#define SS 2048
#define DD 768
#define BS (BB*SS)
#define OCHUNKS 16
#define OPER (DD/OCHUNKS)   // 48

// ---------------- device scratch (no allocations allowed) ----------------
__device__ float d_part[OCHUNKS][DD*3];  // partial weff sums per o-chunk
__device__ float d_weff[DD*3 + 8];       // [d*3+k]; beff at [DD*3]
__device__ float d_g[BS*3];              // G[b*S+t][k]
__device__ float d_alpha[BS];
__device__ int   d_tend[BS];
__device__ float d_wbeg[BS + 8];
__device__ float d_wend[BS];
__device__ int   d_nf[BB];

// ---------------- 1a) partial weff: grid (9, 16), coalesced over j ----------------
__global__ void k_weff(const float* __restrict__ conv_w, const float* __restrict__ lin_w) {
    int j = blockIdx.x * 256 + threadIdx.x;          // 0..2303
    if (j >= DD*3) return;
    int o0 = blockIdx.y * OPER;
    float s = 0.f;
    #pragma unroll 8
    for (int oo = 0; oo < OPER; ++oo) {
        int o = o0 + oo;
        s = fmaf(__ldg(&lin_w[o]), conv_w[(size_t)o * (DD*3) + j], s);
    }
    d_part[blockIdx.y][j] = s;
}

// ---------------- 1b) reduce partials (deterministic) + beff ----------------
__global__ void k_weff2(const float* __restrict__ conv_b,
                        const float* __restrict__ lin_w, const float* __restrict__ lin_b) {
    if (blockIdx.x < 9) {
        int j = blockIdx.x * 256 + threadIdx.x;
        if (j < DD*3) {
            float s = 0.f;
            #pragma unroll
            for (int c = 0; c < OCHUNKS; ++c) s += d_part[c][j];
            d_weff[j] = s;
        }
    } else {
        __shared__ float red[256];
        int t = threadIdx.x;
        float s = 0.f;
        for (int o = t; o < DD; o += 256) s = fmaf(lin_w[o], conv_b[o], s);
        red[t] = s;
        __syncthreads();
        for (int off = 128; off; off >>= 1) {
            if (t < off) red[t] += red[t + off];
            __syncthreads();
        }
        if (t == 0) d_weff[DD*3] = red[0] + lin_b[0];
    }
}

// ---------------- 2) G[b,t,k]: one warp per row, float4 ----------------
__global__ void k_g(const float* __restrict__ x) {
    __shared__ float s0[DD], s1[DD], s2[DD];
    for (int i = threadIdx.x; i < DD; i += blockDim.x) {
        s0[i] = d_weff[i*3+0];
        s1[i] = d_weff[i*3+1];
        s2[i] = d_weff[i*3+2];
    }
    __syncthreads();
    int warp = threadIdx.x >> 5, lane = threadIdx.x & 31;
    int row  = blockIdx.x * (blockDim.x >> 5) + warp;    // 0..BS-1
    if (row >= BS) return;
    const float4* xr = (const float4*)(x + (size_t)row * DD);
    const float4* w0 = (const float4*)s0;
    const float4* w1 = (const float4*)s1;
    const float4* w2 = (const float4*)s2;
    float a0 = 0.f, a1 = 0.f, a2 = 0.f;
    #pragma unroll
    for (int i = 0; i < DD/128; ++i) {                   // 6 iterations
        int d4 = lane + i*32;
        float4 v = xr[d4];
        float4 c0 = w0[d4], c1 = w1[d4], c2 = w2[d4];
        a0 = fmaf(v.x, c0.x, fmaf(v.y, c0.y, fmaf(v.z, c0.z, fmaf(v.w, c0.w, a0))));
        a1 = fmaf(v.x, c1.x, fmaf(v.y, c1.y, fmaf(v.z, c1.z, fmaf(v.w, c1.w, a1))));
        a2 = fmaf(v.x, c2.x, fmaf(v.y, c2.y, fmaf(v.z, c2.z, fmaf(v.w, c2.w, a2))));
    }
    #pragma unroll
    for (int o = 16; o; o >>= 1) {
        a0 += __shfl_xor_sync(0xFFFFFFFFu, a0, o);
        a1 += __shfl_xor_sync(0xFFFFFFFFu, a1, o);
        a2 += __shfl_xor_sync(0xFFFFFFFFu, a2, o);
    }
    if (lane == 0) {
        d_g[row*3+0] = a0; d_g[row*3+1] = a1; d_g[row*3+2] = a2;
    }
}

// ---------------- 3) fused alpha + scalar CIF scan + parallel compaction ----------------
// Staging (256 thr): alpha = sigmoid(g-window), to SMEM + d_alpha.
// Thread 0: minimal 12-cyc/step chain, stores only aacc-history to SMEM.
// Compaction (256 thr): recompute fire/a1/a2 bit-exactly, prefix-scan, write tables.
__global__ void k_scan(const int* __restrict__ lens, float* __restrict__ out_len, int write_len) {
    __shared__ float sa[SS];      // alphas
    __shared__ float sacc[SS];    // aacc BEFORE each step
    __shared__ int   wsum[8];
    int b   = blockIdx.x;
    int tid = threadIdx.x;
    int base = b * SS;
    int len = lens[b];
    if (len > SS) len = SS;
    if (len < 0)  len = 0;

    // --- staging: compute alphas from g ---
    float beff = d_weff[DD*3];
    for (int s = tid; s < SS; s += 256) {
        int idx = base + s;
        float pre = beff + d_g[idx*3 + 1];
        if (s > 0)    pre += d_g[(idx-1)*3 + 0];
        if (s < SS-1) pre += d_g[(idx+1)*3 + 2];
        float a = 1.f / (1.f + expf(-pre));
        sa[s] = a;
        d_alpha[idx] = a;
    }
    __syncthreads();

    // --- sequential chain: thread 0 only ---
    if (tid == 0) {
        float aacc = 0.f;
        #pragma unroll 8
        for (int t = 0; t < len; ++t) {
            sacc[t] = aacc;
            float a = sa[t];
            float aacc_u = aacc + a;
            float a1 = 1.0f - aacc;      // ref op order
            float a2 = a - a1;
            aacc = (aacc_u >= 1.0f) ? a2 : aacc_u;
        }
        d_wbeg[base] = 0.f;
    }
    __syncthreads();

    // --- parallel compaction: 8 steps per thread ---
    int t0 = tid * 8;
    unsigned f[8];
    int cnt = 0;
    #pragma unroll
    for (int i = 0; i < 8; ++i) {
        int t = t0 + i;
        unsigned fire = 0;
        if (t < len) {
            float ab = sacc[t];
            float a  = sa[t];
            fire = ((ab + a) >= 1.0f) ? 1u : 0u;   // identical rounding to chain
        }
        f[i] = fire;
        cnt += (int)fire;
    }
    int lane = tid & 31, w = tid >> 5;
    int inc = cnt;
    #pragma unroll
    for (int o = 1; o < 32; o <<= 1) {
        int v = __shfl_up_sync(0xFFFFFFFFu, inc, o);
        if (lane >= o) inc += v;
    }
    if (lane == 31) wsum[w] = inc;
    __syncthreads();
    int woff = 0;
    #pragma unroll
    for (int i = 0; i < 8; ++i) woff += (i < w) ? wsum[i] : 0;
    int pos = base + woff + inc - cnt;    // exclusive prefix
    #pragma unroll
    for (int i = 0; i < 8; ++i) {
        if (f[i]) {
            int t = t0 + i;
            float ab = sacc[t];
            float a  = sa[t];
            float a1 = 1.0f - ab;
            float a2 = a - a1;
            d_tend[pos] = t;
            d_wend[pos] = a1;
            d_wbeg[pos + 1] = a2;
            pos++;
        }
    }
    if (tid == 255) {
        int total = woff + inc;
        d_nf[b] = total;
        if (write_len) out_len[b] = (float)total;
    }
}

// ---------------- 4) emit: segmented weighted sum, float4, 192 thr/block ----------------
__global__ void k_emit(const float* __restrict__ x, float* __restrict__ out) {
    int r = blockIdx.x, b = blockIdx.y;
    int tid = threadIdx.x;
    float4* orow = (float4*)(out + ((size_t)b*SS + r) * DD);
    int nf = d_nf[b];
    if (r >= nf) {
        orow[tid] = make_float4(0.f, 0.f, 0.f, 0.f);
        return;
    }
    int base = b*SS;
    int t1 = d_tend[base + r];
    int t0 = (r == 0) ? -1 : d_tend[base + r - 1];
    const float4* xb = (const float4*)(x + (size_t)b*SS*DD);
    float4 acc = make_float4(0.f, 0.f, 0.f, 0.f);
    if (r > 0) {
        float w = d_wbeg[base + r];
        float4 v = xb[(size_t)t0 * (DD/4) + tid];
        acc.x = w*v.x; acc.y = w*v.y; acc.z = w*v.z; acc.w = w*v.w;
    }
    for (int t = t0 + 1; t < t1; ++t) {
        float w = d_alpha[base + t];
        float4 v = xb[(size_t)t * (DD/4) + tid];
        acc.x = fmaf(w, v.x, acc.x); acc.y = fmaf(w, v.y, acc.y);
        acc.z = fmaf(w, v.z, acc.z); acc.w = fmaf(w, v.w, acc.w);
    }
    {
        float w = d_wend[base + r];
        float4 v = xb[(size_t)t1 * (DD/4) + tid];
        acc.x = fmaf(w, v.x, acc.x); acc.y = fmaf(w, v.y, acc.y);
        acc.z = fmaf(w, v.z, acc.z); acc.w = fmaf(w, v.w, acc.w);
    }
    orow[tid] = acc;
}

extern "C" void kernel_launch(void* const* d_in, const int* in_sizes, int n_in,
                              void* d_out, int out_size) {
    const float* x      = (const float*)d_in[0];   // (B,S,D) f32
    const int*   lens   = (const int*)  d_in[1];   // (B,) i32
    const float* conv_w = (const float*)d_in[2];   // (D,D,3)
    const float* conv_b = (const float*)d_in[3];   // (D,)
    const float* lin_w  = (const float*)d_in[4];   // (1,D)
    const float* lin_b  = (const float*)d_in[5];   // (1,)
    float* out = (float*)d_out;

    const int BSD = BB * SS * DD;
    int write_len = (out_size >= BSD + BB) ? 1 : 0;

    k_weff <<<dim3(9, OCHUNKS), 256>>>(conv_w, lin_w);
    k_weff2<<<10, 256>>>(conv_b, lin_w, lin_b);
    k_g    <<<BS / 8, 256>>>(x);
    k_scan <<<BB, 256>>>(lens, out + BSD, write_len);
    k_emit <<<dim3(SS, BB), 192>>>(x, out);
}

// round 8
// speedup vs baseline: 1.2883x; 1.2883x over previous
#include <cuda_runtime.h>
#include <math.h>

#define BB 16
#define SS 2048
#define DD 768
#define BS (BB*SS)
#define OCHUNKS 16
#define OPER (DD/OCHUNKS)   // 48

// ---------------- device scratch (no allocations allowed) ----------------
__device__ float d_part[OCHUNKS][DD*3];  // partial weff sums per o-chunk
__device__ float d_weff[DD*3 + 8];       // [d*3+k]; beff at [DD*3]
__device__ float d_g[BS*3];              // G[b*S+t][k]
__device__ float d_alpha[BS];
__device__ int   d_tend[BS];
__device__ float d_wbeg[BS + 8];
__device__ float d_wend[BS];
__device__ int   d_nf[BB];

// ---------------- 1a) partial weff: grid (9, 16), coalesced over j ----------------
__global__ void k_weff(const float* __restrict__ conv_w, const float* __restrict__ lin_w) {
    int j = blockIdx.x * 256 + threadIdx.x;          // 0..2303
    if (j >= DD*3) return;
    int o0 = blockIdx.y * OPER;
    float s = 0.f;
    #pragma unroll 8
    for (int oo = 0; oo < OPER; ++oo) {
        int o = o0 + oo;
        s = fmaf(__ldg(&lin_w[o]), conv_w[(size_t)o * (DD*3) + j], s);
    }
    d_part[blockIdx.y][j] = s;
}

// ---------------- 1b) reduce partials (deterministic) + beff ----------------
__global__ void k_weff2(const float* __restrict__ conv_b,
                        const float* __restrict__ lin_w, const float* __restrict__ lin_b) {
    if (blockIdx.x < 9) {
        int j = blockIdx.x * 256 + threadIdx.x;
        if (j < DD*3) {
            float s = 0.f;
            #pragma unroll
            for (int c = 0; c < OCHUNKS; ++c) s += d_part[c][j];
            d_weff[j] = s;
        }
    } else {
        __shared__ float red[256];
        int t = threadIdx.x;
        float s = 0.f;
        for (int o = t; o < DD; o += 256) s = fmaf(lin_w[o], conv_b[o], s);
        red[t] = s;
        __syncthreads();
        for (int off = 128; off; off >>= 1) {
            if (t < off) red[t] += red[t + off];
            __syncthreads();
        }
        if (t == 0) d_weff[DD*3] = red[0] + lin_b[0];
    }
}

// ---------------- 2) G[b,t,k]: one warp per row, float4 ----------------
__global__ void k_g(const float* __restrict__ x) {
    __shared__ float s0[DD], s1[DD], s2[DD];
    for (int i = threadIdx.x; i < DD; i += blockDim.x) {
        s0[i] = d_weff[i*3+0];
        s1[i] = d_weff[i*3+1];
        s2[i] = d_weff[i*3+2];
    }
    __syncthreads();
    int warp = threadIdx.x >> 5, lane = threadIdx.x & 31;
    int row  = blockIdx.x * (blockDim.x >> 5) + warp;    // 0..BS-1
    if (row >= BS) return;
    const float4* xr = (const float4*)(x + (size_t)row * DD);
    const float4* w0 = (const float4*)s0;
    const float4* w1 = (const float4*)s1;
    const float4* w2 = (const float4*)s2;
    float a0 = 0.f, a1 = 0.f, a2 = 0.f;
    #pragma unroll
    for (int i = 0; i < DD/128; ++i) {                   // 6 iterations
        int d4 = lane + i*32;
        float4 v = xr[d4];
        float4 c0 = w0[d4], c1 = w1[d4], c2 = w2[d4];
        a0 = fmaf(v.x, c0.x, fmaf(v.y, c0.y, fmaf(v.z, c0.z, fmaf(v.w, c0.w, a0))));
        a1 = fmaf(v.x, c1.x, fmaf(v.y, c1.y, fmaf(v.z, c1.z, fmaf(v.w, c1.w, a1))));
        a2 = fmaf(v.x, c2.x, fmaf(v.y, c2.y, fmaf(v.z, c2.z, fmaf(v.w, c2.w, a2))));
    }
    #pragma unroll
    for (int o = 16; o; o >>= 1) {
        a0 += __shfl_xor_sync(0xFFFFFFFFu, a0, o);
        a1 += __shfl_xor_sync(0xFFFFFFFFu, a1, o);
        a2 += __shfl_xor_sync(0xFFFFFFFFu, a2, o);
    }
    if (lane == 0) {
        d_g[row*3+0] = a0; d_g[row*3+1] = a1; d_g[row*3+2] = a2;
    }
}

// ---------------- 3) fused alpha + pipelined scalar CIF chain + parallel compaction ----
__global__ void k_scan(const int* __restrict__ lens, float* __restrict__ out_len, int write_len) {
    __shared__ float sa[SS];      // alphas (zero beyond len)
    __shared__ float sacc[SS];    // aacc BEFORE each step
    __shared__ int   wsum[8];
    int b   = blockIdx.x;
    int tid = threadIdx.x;
    int base = b * SS;
    int len = lens[b];
    if (len > SS) len = SS;
    if (len < 0)  len = 0;

    // --- staging: compute alphas from g; pad sa with 0 beyond len (no-op steps) ---
    float beff = d_weff[DD*3];
    #pragma unroll
    for (int i = 0; i < SS/256; ++i) {
        int s = tid + i*256;
        int idx = base + s;
        float pre = beff + d_g[idx*3 + 1];
        if (s > 0)    pre += d_g[(idx-1)*3 + 0];
        if (s < SS-1) pre += d_g[(idx+1)*3 + 2];
        float a = 1.f / (1.f + expf(-pre));
        d_alpha[idx] = a;
        sa[s] = (s < len) ? a : 0.f;
    }
    __syncthreads();

    // --- sequential chain: thread 0, software-pipelined register prefetch ---
    if (tid == 0) {
        float aacc = 0.f;
        int nsteps = (len + 7) & ~7;          // zero-padded alphas make tail steps no-ops
        float cur[8];
        #pragma unroll
        for (int i = 0; i < 8; ++i) cur[i] = sa[i];
        for (int c = 0; c < nsteps; c += 8) {
            float nxt[8];
            int cn = (c + 8) & (SS - 1);      // wrapped; values unused on final iter
            #pragma unroll
            for (int i = 0; i < 8; ++i) nxt[i] = sa[cn + i];
            #pragma unroll
            for (int i = 0; i < 8; ++i) {
                sacc[c + i] = aacc;
                float a  = cur[i];
                float u  = aacc + a;          // exact ref op order
                float a1 = 1.0f - aacc;
                float a2 = a - a1;
                aacc = (u >= 1.0f) ? a2 : u;
            }
            #pragma unroll
            for (int i = 0; i < 8; ++i) cur[i] = nxt[i];
        }
        d_wbeg[base] = 0.f;
    }
    __syncthreads();

    // --- parallel compaction: recompute fires bit-exactly, prefix-scan, write tables ---
    int t0 = tid * 8;
    unsigned f[8];
    int cnt = 0;
    #pragma unroll
    for (int i = 0; i < 8; ++i) {
        int t = t0 + i;
        unsigned fire = 0;
        if (t < len) {
            float ab = sacc[t];
            float a  = sa[t];
            fire = ((ab + a) >= 1.0f) ? 1u : 0u;   // identical rounding to chain
        }
        f[i] = fire;
        cnt += (int)fire;
    }
    int lane = tid & 31, w = tid >> 5;
    int inc = cnt;
    #pragma unroll
    for (int o = 1; o < 32; o <<= 1) {
        int v = __shfl_up_sync(0xFFFFFFFFu, inc, o);
        if (lane >= o) inc += v;
    }
    if (lane == 31) wsum[w] = inc;
    __syncthreads();
    int woff = 0;
    #pragma unroll
    for (int i = 0; i < 8; ++i) woff += (i < w) ? wsum[i] : 0;
    int pos = base + woff + inc - cnt;    // exclusive prefix
    #pragma unroll
    for (int i = 0; i < 8; ++i) {
        if (f[i]) {
            int t = t0 + i;
            float ab = sacc[t];
            float a  = sa[t];
            float a1 = 1.0f - ab;
            float a2 = a - a1;
            d_tend[pos] = t;
            d_wend[pos] = a1;
            d_wbeg[pos + 1] = a2;
            pos++;
        }
    }
    if (tid == 255) {
        int total = woff + inc;
        d_nf[b] = total;
        if (write_len) out_len[b] = (float)total;
    }
}

// ---------------- 4) emit: segmented weighted sum, float4, 192 thr/block ----------------
__global__ void k_emit(const float* __restrict__ x, float* __restrict__ out) {
    int r = blockIdx.x, b = blockIdx.y;
    int tid = threadIdx.x;
    float4* orow = (float4*)(out + ((size_t)b*SS + r) * DD);
    int nf = d_nf[b];
    if (r >= nf) {
        orow[tid] = make_float4(0.f, 0.f, 0.f, 0.f);
        return;
    }
    int base = b*SS;
    int t1 = d_tend[base + r];
    int t0 = (r == 0) ? -1 : d_tend[base + r - 1];
    const float4* xb = (const float4*)(x + (size_t)b*SS*DD);
    float4 acc = make_float4(0.f, 0.f, 0.f, 0.f);
    if (r > 0) {
        float w = d_wbeg[base + r];
        float4 v = xb[(size_t)t0 * (DD/4) + tid];
        acc.x = w*v.x; acc.y = w*v.y; acc.z = w*v.z; acc.w = w*v.w;
    }
    for (int t = t0 + 1; t < t1; ++t) {
        float w = d_alpha[base + t];
        float4 v = xb[(size_t)t * (DD/4) + tid];
        acc.x = fmaf(w, v.x, acc.x); acc.y = fmaf(w, v.y, acc.y);
        acc.z = fmaf(w, v.z, acc.z); acc.w = fmaf(w, v.w, acc.w);
    }
    {
        float w = d_wend[base + r];
        float4 v = xb[(size_t)t1 * (DD/4) + tid];
        acc.x = fmaf(w, v.x, acc.x); acc.y = fmaf(w, v.y, acc.y);
        acc.z = fmaf(w, v.z, acc.z); acc.w = fmaf(w, v.w, acc.w);
    }
    orow[tid] = acc;
}

extern "C" void kernel_launch(void* const* d_in, const int* in_sizes, int n_in,
                              void* d_out, int out_size) {
    const float* x      = (const float*)d_in[0];   // (B,S,D) f32
    const int*   lens   = (const int*)  d_in[1];   // (B,) i32
    const float* conv_w = (const float*)d_in[2];   // (D,D,3)
    const float* conv_b = (const float*)d_in[3];   // (D,)
    const float* lin_w  = (const float*)d_in[4];   // (1,D)
    const float* lin_b  = (const float*)d_in[5];   // (1,)
    float* out = (float*)d_out;

    const int BSD = BB * SS * DD;
    int write_len = (out_size >= BSD + BB) ? 1 : 0;

    k_weff <<<dim3(9, OCHUNKS), 256>>>(conv_w, lin_w);
    k_weff2<<<10, 256>>>(conv_b, lin_w, lin_b);
    k_g    <<<BS / 8, 256>>>(x);
    k_scan <<<BB, 256>>>(lens, out + BSD, write_len);
    k_emit <<<dim3(SS, BB), 192>>>(x, out);
}